// round 6
// baseline (speedup 1.0000x reference)
#include <cuda_runtime.h>
#include <cuda_fp16.h>
#include <cstdint>

// y[m,o] = scale[o]*( dot(x[m], q[o]) - zp[o]*rowsum(x[m]) ) + bias[o]
// q codes in [0,255] are EXACT in fp16 -> fp16 HMMA, fp32 accumulate.
// (tcgen05 unavailable: harness PTX target is compute_103, not 103a.)
//
// R5 post-mortem: HMMA.16816 f32-acc rt ~= 8 cyc/SMSP -> ~1.28ms GEMM floor;
// we're at 81%. This round halves barrier events (BK=32, 6-stage ring, one
// sync per 2 K-tiles), fixes the tail wait_group race, merges conversions.

static constexpr int M_TOTAL = 8192;    // 4*2048
static constexpr int K_TOTAL = 4096;
static constexpr int N_TOTAL = 11008;

static constexpr int BM = 128, BN = 128, BK = 32;   // BK halves = 64B rows
static constexpr int KTILES = K_TOTAL / BK;         // 128
static constexpr int SUPER  = KTILES / 2;           // 64 (2 K-tiles / sync)
static constexpr int STAGES = 6;                    // 3 batches of 2 stages
static constexpr int NUM_M = M_TOTAL / BM;          // 64
static constexpr int NUM_N = N_TOTAL / BN;          // 86
static constexpr int GROUP_M = 16;

static constexpr int A_STAGE = BM * BK;             // halves (4096)
static constexpr int STAGE_H = (BM + BN) * BK;      // 8192 halves = 16KB
static constexpr int SMEM_BYTES = STAGES * STAGE_H * 2;  // 96KB -> 2 CTAs/SM

// Scratch (static __device__ arrays: allocation-free per harness rules)
__device__ __half g_Xh[(size_t)M_TOTAL * K_TOTAL];
__device__ __half g_Wh[(size_t)N_TOTAL * K_TOTAL];
__device__ float  g_rowsum[M_TOTAL];

// ---------------------------------------------------------------------------
__device__ __forceinline__ int swz(int row, int chunk) {
    // 64B rows, 4x16B chunks, xor-swizzle (2-way LDS conflict: hidden by MMA)
    return row * BK + ((chunk ^ (row & 3)) << 3);
}
__device__ __forceinline__ void cp_async16(void* s, const void* g) {
    uint32_t sa = (uint32_t)__cvta_generic_to_shared(s);
    asm volatile("cp.async.cg.shared.global [%0], [%1], 16;" :: "r"(sa), "l"(g));
}
__device__ __forceinline__ void cp_commit() { asm volatile("cp.async.commit_group;"); }

__device__ __forceinline__ void ldm_x4(uint32_t* r, const __half* p) {
    uint32_t sa = (uint32_t)__cvta_generic_to_shared(p);
    asm volatile("ldmatrix.sync.aligned.m8n8.x4.shared.b16 {%0,%1,%2,%3}, [%4];"
                 : "=r"(r[0]), "=r"(r[1]), "=r"(r[2]), "=r"(r[3]) : "r"(sa));
}
__device__ __forceinline__ void mma16816(float* c, const uint32_t* a, const uint32_t* b) {
    asm volatile(
        "mma.sync.aligned.m16n8k16.row.col.f32.f16.f16.f32 "
        "{%0,%1,%2,%3}, {%4,%5,%6,%7}, {%8,%9}, {%0,%1,%2,%3};"
        : "+f"(c[0]), "+f"(c[1]), "+f"(c[2]), "+f"(c[3])
        : "r"(a[0]), "r"(a[1]), "r"(a[2]), "r"(a[3]), "r"(b[0]), "r"(b[1]));
}

// ---------------------------------------------------------------------------
// fused conversion: blocks [0,8192) do x rows (+rowsum); rest convert W.
// ---------------------------------------------------------------------------
__global__ void convert_fused_kernel(const float* __restrict__ x,
                                     const int* __restrict__ q) {
    if (blockIdx.x < M_TOTAL) {
        const int row = blockIdx.x;
        const float* xr = x + (size_t)row * K_TOTAL;
        __half* xo = g_Xh + (size_t)row * K_TOTAL;
        float s = 0.f;
        for (int i = threadIdx.x * 4; i < K_TOTAL; i += blockDim.x * 4) {
            float4 v = *(const float4*)(xr + i);
            s += v.x + v.y + v.z + v.w;
            *(__half2*)(xo + i)     = __floats2half2_rn(v.x, v.y);
            *(__half2*)(xo + i + 2) = __floats2half2_rn(v.z, v.w);
        }
        #pragma unroll
        for (int off = 16; off; off >>= 1) s += __shfl_down_sync(~0u, s, off);
        __shared__ float ws[8];
        if ((threadIdx.x & 31) == 0) ws[threadIdx.x >> 5] = s;
        __syncthreads();
        if (threadIdx.x < 8) {
            float v = ws[threadIdx.x];
            #pragma unroll
            for (int off = 4; off; off >>= 1) v += __shfl_down_sync(0xffu, v, off);
            if (threadIdx.x == 0) g_rowsum[row] = v;
        }
    } else {
        const size_t total4 = (size_t)N_TOTAL * K_TOTAL / 4;
        const size_t stride = (size_t)(gridDim.x - M_TOTAL) * blockDim.x;
        for (size_t i = (size_t)(blockIdx.x - M_TOTAL) * blockDim.x + threadIdx.x;
             i < total4; i += stride) {
            int4 v = ((const int4*)q)[i];
            __half2* o = (__half2*)(g_Wh + i * 4);
            o[0] = __halves2half2(__int2half_rn(v.x), __int2half_rn(v.y));
            o[1] = __halves2half2(__int2half_rn(v.z), __int2half_rn(v.w));
        }
    }
}

// ---------------------------------------------------------------------------
// GEMM: 128x128 CTA tile, 8 warps (4m x 2n) -> warp tile 32x64.
// BK=32 K-tiles, 6-stage cp.async ring, ONE wait+sync per 2 K-tiles.
// ---------------------------------------------------------------------------
__global__ void __launch_bounds__(256, 2) woq_gemm_kernel(
    const float* __restrict__ scales, const float* __restrict__ zps,
    const float* __restrict__ bias, float* __restrict__ out)
{
    extern __shared__ __half smem[];

    const int tid  = threadIdx.x;
    const int lane = tid & 31;
    const int warp = tid >> 5;
    const int wm = warp & 3;   // 0..3 -> 32 rows each
    const int wn = warp >> 2;  // 0..1 -> 64 cols each

    // grouped-M rasterization -> L2-resident wave working set
    const int bid = blockIdx.x;
    const int g   = bid / (GROUP_M * NUM_N);
    const int r   = bid % (GROUP_M * NUM_N);
    const int bm  = (g * GROUP_M + (r % GROUP_M)) * BM;
    const int bn  = (r / GROUP_M) * BN;

    // Coalesced loaders: thread t -> row t/4 (+64 per pass), 16B chunk t%4.
    const int lrow   = tid >> 2;   // 0..63
    const int lchunk = tid & 3;    // 0..3
    const int schunk = (lchunk ^ (lrow & 3)) << 3;   // swizzled half-offset
    const __half* gA = g_Xh + (size_t)(bm + lrow) * K_TOTAL + lchunk * 8;
    const __half* gB = g_Wh + (size_t)(bn + lrow) * K_TOTAL + lchunk * 8;

    auto load_stage = [&](int s, int kt) {
        __half* sa = smem + s * STAGE_H;
        __half* sb = sa + A_STAGE;
        const __half* ga = gA + kt * BK;
        const __half* gb = gB + kt * BK;
        #pragma unroll
        for (int p = 0; p < 2; p++) {
            const int ro = (lrow + p * 64) * BK + schunk;
            cp_async16(sa + ro, ga + (size_t)(p * 64) * K_TOTAL);
            cp_async16(sb + ro, gb + (size_t)(p * 64) * K_TOTAL);
        }
    };

    float c[2][8][4];
    #pragma unroll
    for (int i = 0; i < 2; i++)
        #pragma unroll
        for (int j = 0; j < 8; j++)
            #pragma unroll
            for (int k = 0; k < 4; k++) c[i][j][k] = 0.f;

    // ldmatrix lane addressing (chunk units of 16B within 64B rows)
    const int mat    = lane >> 3;
    const int arow0  = wm * 32 + (mat & 1) * 8 + (lane & 7);      // + mi*16
    const int achunk = mat >> 1;                                   // + kc*2
    const int brow0  = wn * 64 + ((mat >> 1) << 3) + (lane & 7);   // + nj*16
    const int bchunk = mat & 1;                                    // + kc*2

    auto mma_tile = [&](int s) {
        const __half* sa = smem + s * STAGE_H;
        const __half* sb = sa + A_STAGE;
        #pragma unroll
        for (int kc = 0; kc < 2; kc++) {
            uint32_t a[2][4];
            #pragma unroll
            for (int mi = 0; mi < 2; mi++)
                ldm_x4(a[mi], sa + swz(arow0 + mi * 16, kc * 2 + achunk));
            uint32_t b[8][2];
            #pragma unroll
            for (int nj = 0; nj < 4; nj++) {
                uint32_t t[4];
                ldm_x4(t, sb + swz(brow0 + nj * 16, kc * 2 + bchunk));
                b[nj*2  ][0] = t[0]; b[nj*2  ][1] = t[1];
                b[nj*2+1][0] = t[2]; b[nj*2+1][1] = t[3];
            }
            #pragma unroll
            for (int mi = 0; mi < 2; mi++)
                #pragma unroll
                for (int nt = 0; nt < 8; nt++)
                    mma16816(c[mi][nt], a[mi], b[nt]);
        }
    };

    // prologue: 2 batches (4 stages) in flight
    load_stage(0, 0); load_stage(1, 1); cp_commit();   // batch 0
    load_stage(2, 2); load_stage(3, 3); cp_commit();   // batch 1

    int scons = 0;                 // consuming stage pair {scons, scons+1}
    for (int j = 0; j < SUPER; j++) {
        // tail: empty groups retire instantly, so wait_group(1) could leave
        // the final REAL batch pending -> use wait_group(0) on last 2 iters.
        if (j < SUPER - 2) asm volatile("cp.async.wait_group 1;");
        else               asm volatile("cp.async.wait_group 0;");
        __syncthreads();

        if (j + 2 < SUPER) {
            const int sl = scons >= 2 ? scons - 2 : scons + 4;  // (scons+4)%6
            load_stage(sl,     2 * (j + 2));
            load_stage(sl + 1, 2 * (j + 2) + 1);
        }
        cp_commit();

        mma_tile(scons);
        mma_tile(scons + 1);
        scons = scons >= 4 ? 0 : scons + 2;
    }

    // epilogue: y = s*(acc - zp*rowsum) + bias
    const int er = lane >> 2;        // row within 8
    const int ec = (lane & 3) * 2;   // col pair within 8

    float rs[2][2];
    #pragma unroll
    for (int mi = 0; mi < 2; mi++)
        #pragma unroll
        for (int h = 0; h < 2; h++)
            rs[mi][h] = g_rowsum[bm + wm*32 + mi*16 + h*8 + er];

    #pragma unroll
    for (int nt = 0; nt < 8; nt++) {
        const int gn = bn + wn*64 + nt*8 + ec;
        const float s0 = scales[gn],  s1 = scales[gn+1];
        const float z0 = zps[gn],     z1 = zps[gn+1];
        const float b0 = bias[gn],    b1 = bias[gn+1];
        #pragma unroll
        for (int mi = 0; mi < 2; mi++) {
            #pragma unroll
            for (int h = 0; h < 2; h++) {
                const int gm = bm + wm*32 + mi*16 + h*8 + er;
                float2 v;
                v.x = s0 * (c[mi][nt][h*2+0] - z0 * rs[mi][h]) + b0;
                v.y = s1 * (c[mi][nt][h*2+1] - z1 * rs[mi][h]) + b1;
                *(float2*)(out + (size_t)gm * N_TOTAL + gn) = v;
            }
        }
    }
}

// ---------------------------------------------------------------------------
extern "C" void kernel_launch(void* const* d_in, const int* in_sizes, int n_in,
                              void* d_out, int out_size) {
    const float* x  = (const float*)d_in[0];
    const int*   qw = (const int*)d_in[1];
    const float* sc = (const float*)d_in[2];
    const float* zp = (const float*)d_in[3];
    const float* bi = (const float*)d_in[4];
    float* out = (float*)d_out;

    convert_fused_kernel<<<M_TOTAL + 8192, 256>>>(x, qw);

    cudaFuncSetAttribute(woq_gemm_kernel,
                         cudaFuncAttributeMaxDynamicSharedMemorySize, SMEM_BYTES);
    woq_gemm_kernel<<<NUM_M * NUM_N, 256, SMEM_BYTES>>>(sc, zp, bi, out);
}

// round 7
// speedup vs baseline: 1.5167x; 1.5167x over previous
#include <cuda_runtime.h>
#include <cuda_fp16.h>
#include <cstdint>

// y[m,o] = scale[o]*( dot(x[m], q[o]) - zp[o]*rowsum(x[m]) ) + bias[o]
// q codes in [0,255] are EXACT in fp16 -> fp16 HMMA, fp32 accumulate.
// (tcgen05 unavailable: harness PTX target is compute_103, not 103a.)
//
// R6 post-mortem: BK=32 swizzle broke ldmatrix conflict-freedom -> L1-bound
// (l1=79.8%, tensor=50.2%). The BK=64 / 128B-row swizzle is load-bearing.
// This round: R5 GEMM verbatim (proven 1645us) + fused conversion kernel.

static constexpr int M_TOTAL = 8192;    // 4*2048
static constexpr int K_TOTAL = 4096;
static constexpr int N_TOTAL = 11008;

static constexpr int BM = 128, BN = 128, BK = 64;   // BK halves = 128B rows
static constexpr int KTILES = K_TOTAL / BK;         // 64
static constexpr int STAGES = 3;
static constexpr int NUM_M = M_TOTAL / BM;          // 64
static constexpr int NUM_N = N_TOTAL / BN;          // 86
static constexpr int GROUP_M = 16;

static constexpr int A_STAGE = BM * BK;             // halves
static constexpr int B_STAGE = BN * BK;
static constexpr int STAGE_H = A_STAGE + B_STAGE;   // 16384 halves = 32KB
static constexpr int SMEM_BYTES = STAGES * STAGE_H * 2;  // 96KB -> 2 CTAs/SM

// Scratch (static __device__ arrays: allocation-free per harness rules)
__device__ __half g_Xh[(size_t)M_TOTAL * K_TOTAL];
__device__ __half g_Wh[(size_t)N_TOTAL * K_TOTAL];
__device__ float  g_rowsum[M_TOTAL];

// ---------------------------------------------------------------------------
__device__ __forceinline__ int swz(int row, int chunk) {
    // 128B rows, 8x16B chunks, xor swizzle -> conflict-free ldmatrix/cp.async
    return row * BK + ((chunk ^ (row & 7)) << 3);
}
__device__ __forceinline__ void cp_async16(void* s, const void* g) {
    uint32_t sa = (uint32_t)__cvta_generic_to_shared(s);
    asm volatile("cp.async.cg.shared.global [%0], [%1], 16;" :: "r"(sa), "l"(g));
}
__device__ __forceinline__ void cp_commit() { asm volatile("cp.async.commit_group;"); }

__device__ __forceinline__ void ldm_x4(uint32_t* r, const __half* p) {
    uint32_t sa = (uint32_t)__cvta_generic_to_shared(p);
    asm volatile("ldmatrix.sync.aligned.m8n8.x4.shared.b16 {%0,%1,%2,%3}, [%4];"
                 : "=r"(r[0]), "=r"(r[1]), "=r"(r[2]), "=r"(r[3]) : "r"(sa));
}
__device__ __forceinline__ void mma16816(float* c, const uint32_t* a, const uint32_t* b) {
    asm volatile(
        "mma.sync.aligned.m16n8k16.row.col.f32.f16.f16.f32 "
        "{%0,%1,%2,%3}, {%4,%5,%6,%7}, {%8,%9}, {%0,%1,%2,%3};"
        : "+f"(c[0]), "+f"(c[1]), "+f"(c[2]), "+f"(c[3])
        : "r"(a[0]), "r"(a[1]), "r"(a[2]), "r"(a[3]), "r"(b[0]), "r"(b[1]));
}

// ---------------------------------------------------------------------------
// fused conversion: blocks [0,8192) do x rows (+rowsum); rest convert W.
// ---------------------------------------------------------------------------
__global__ void convert_fused_kernel(const float* __restrict__ x,
                                     const int* __restrict__ q) {
    if (blockIdx.x < M_TOTAL) {
        const int row = blockIdx.x;
        const float* xr = x + (size_t)row * K_TOTAL;
        __half* xo = g_Xh + (size_t)row * K_TOTAL;
        float s = 0.f;
        for (int i = threadIdx.x * 4; i < K_TOTAL; i += blockDim.x * 4) {
            float4 v = *(const float4*)(xr + i);
            s += v.x + v.y + v.z + v.w;
            *(__half2*)(xo + i)     = __floats2half2_rn(v.x, v.y);
            *(__half2*)(xo + i + 2) = __floats2half2_rn(v.z, v.w);
        }
        #pragma unroll
        for (int off = 16; off; off >>= 1) s += __shfl_down_sync(~0u, s, off);
        __shared__ float ws[8];
        if ((threadIdx.x & 31) == 0) ws[threadIdx.x >> 5] = s;
        __syncthreads();
        if (threadIdx.x < 8) {
            float v = ws[threadIdx.x];
            #pragma unroll
            for (int off = 4; off; off >>= 1) v += __shfl_down_sync(0xffu, v, off);
            if (threadIdx.x == 0) g_rowsum[row] = v;
        }
    } else {
        const size_t total4 = (size_t)N_TOTAL * K_TOTAL / 4;
        const size_t stride = (size_t)(gridDim.x - M_TOTAL) * blockDim.x;
        for (size_t i = (size_t)(blockIdx.x - M_TOTAL) * blockDim.x + threadIdx.x;
             i < total4; i += stride) {
            int4 v = ((const int4*)q)[i];
            __half2* o = (__half2*)(g_Wh + i * 4);
            o[0] = __halves2half2(__int2half_rn(v.x), __int2half_rn(v.y));
            o[1] = __halves2half2(__int2half_rn(v.z), __int2half_rn(v.w));
        }
    }
}

// ---------------------------------------------------------------------------
// GEMM: 128x128x64 CTA tile, 8 warps (4m x 2n) -> warp tile 32x64,
// 3-stage cp.async ring (wait_group 1), grouped-M raster, 2 CTAs/SM.
// ---------------------------------------------------------------------------
__global__ void __launch_bounds__(256, 2) woq_gemm_kernel(
    const float* __restrict__ scales, const float* __restrict__ zps,
    const float* __restrict__ bias, float* __restrict__ out)
{
    extern __shared__ __half smem[];

    const int tid  = threadIdx.x;
    const int lane = tid & 31;
    const int warp = tid >> 5;
    const int wm = warp & 3;   // 0..3 -> 32 rows each
    const int wn = warp >> 2;  // 0..1 -> 64 cols each

    // grouped-M rasterization: a wave of CTAs shares a small A panel + few
    // B panels -> L2-resident working set.
    const int bid = blockIdx.x;
    const int g   = bid / (GROUP_M * NUM_N);
    const int r   = bid % (GROUP_M * NUM_N);
    const int bm  = (g * GROUP_M + (r % GROUP_M)) * BM;
    const int bn  = (r / GROUP_M) * BN;

    // Coalesced loaders: thread t -> row t/8 (+32 per pass), 16B chunk t%8.
    const int lrow   = tid >> 3;   // 0..31
    const int lchunk = tid & 7;    // 0..7
    const __half* gA = g_Xh + (size_t)(bm + lrow) * K_TOTAL + lchunk * 8;
    const __half* gB = g_Wh + (size_t)(bn + lrow) * K_TOTAL + lchunk * 8;

    auto load_stage = [&](int s, int kt) {
        __half* sa = smem + s * STAGE_H;
        __half* sb = sa + A_STAGE;
        const __half* ga = gA + kt * BK;
        const __half* gb = gB + kt * BK;
        #pragma unroll
        for (int p = 0; p < 4; p++) {
            cp_async16(sa + swz(lrow + p * 32, lchunk), ga + (size_t)(p * 32) * K_TOTAL);
            cp_async16(sb + swz(lrow + p * 32, lchunk), gb + (size_t)(p * 32) * K_TOTAL);
        }
    };

    float c[2][8][4];
    #pragma unroll
    for (int i = 0; i < 2; i++)
        #pragma unroll
        for (int j = 0; j < 8; j++)
            #pragma unroll
            for (int k = 0; k < 4; k++) c[i][j][k] = 0.f;

    // ldmatrix lane addressing
    const int mat    = lane >> 3;
    const int arow0  = wm * 32 + (mat & 1) * 8 + (lane & 7);     // + mi*16
    const int achunk = mat >> 1;                                  // + kc
    const int brow0  = wn * 64 + ((mat >> 1) << 3) + (lane & 7);  // + nj*16
    const int bchunk = mat & 1;                                   // + kc

    // prologue: 2 stages in flight
    #pragma unroll
    for (int s = 0; s < STAGES - 1; s++) { load_stage(s, s); cp_commit(); }

    for (int kt = 0; kt < KTILES; kt++) {
        const int cur = kt % STAGES;
        asm volatile("cp.async.wait_group %0;" :: "n"(STAGES - 2));
        __syncthreads();

        const int nk = kt + STAGES - 1;
        if (nk < KTILES) load_stage(nk % STAGES, nk);
        cp_commit();   // always commit (possibly empty) so wait count stays exact

        const __half* sa = smem + cur * STAGE_H;
        const __half* sb = sa + A_STAGE;

        #pragma unroll
        for (int kk = 0; kk < 4; kk++) {
            const int kc = kk << 1;
            uint32_t a[2][4];
            #pragma unroll
            for (int mi = 0; mi < 2; mi++)
                ldm_x4(a[mi], sa + swz(arow0 + mi * 16, kc + achunk));
            uint32_t b[8][2];
            #pragma unroll
            for (int nj = 0; nj < 4; nj++) {
                uint32_t t[4];
                ldm_x4(t, sb + swz(brow0 + nj * 16, kc + bchunk));
                b[nj*2  ][0] = t[0]; b[nj*2  ][1] = t[1];
                b[nj*2+1][0] = t[2]; b[nj*2+1][1] = t[3];
            }
            #pragma unroll
            for (int mi = 0; mi < 2; mi++)
                #pragma unroll
                for (int nt = 0; nt < 8; nt++)
                    mma16816(c[mi][nt], a[mi], b[nt]);
        }
    }

    // epilogue: y = s*(acc - zp*rowsum) + bias
    const int er = lane >> 2;        // row within 8
    const int ec = (lane & 3) * 2;   // col pair within 8

    float rs[2][2];
    #pragma unroll
    for (int mi = 0; mi < 2; mi++)
        #pragma unroll
        for (int h = 0; h < 2; h++)
            rs[mi][h] = g_rowsum[bm + wm*32 + mi*16 + h*8 + er];

    #pragma unroll
    for (int nt = 0; nt < 8; nt++) {
        const int gn = bn + wn*64 + nt*8 + ec;
        const float s0 = scales[gn],  s1 = scales[gn+1];
        const float z0 = zps[gn],     z1 = zps[gn+1];
        const float b0 = bias[gn],    b1 = bias[gn+1];
        #pragma unroll
        for (int mi = 0; mi < 2; mi++) {
            #pragma unroll
            for (int h = 0; h < 2; h++) {
                const int gm = bm + wm*32 + mi*16 + h*8 + er;
                float2 v;
                v.x = s0 * (c[mi][nt][h*2+0] - z0 * rs[mi][h]) + b0;
                v.y = s1 * (c[mi][nt][h*2+1] - z1 * rs[mi][h]) + b1;
                *(float2*)(out + (size_t)gm * N_TOTAL + gn) = v;
            }
        }
    }
}

// ---------------------------------------------------------------------------
extern "C" void kernel_launch(void* const* d_in, const int* in_sizes, int n_in,
                              void* d_out, int out_size) {
    const float* x  = (const float*)d_in[0];
    const int*   qw = (const int*)d_in[1];
    const float* sc = (const float*)d_in[2];
    const float* zp = (const float*)d_in[3];
    const float* bi = (const float*)d_in[4];
    float* out = (float*)d_out;

    convert_fused_kernel<<<M_TOTAL + 8192, 256>>>(x, qw);

    cudaFuncSetAttribute(woq_gemm_kernel,
                         cudaFuncAttributeMaxDynamicSharedMemorySize, SMEM_BYTES);
    woq_gemm_kernel<<<NUM_M * NUM_N, 256, SMEM_BYTES>>>(sc, zp, bi, out);
}